// round 11
// baseline (speedup 1.0000x reference)
#include <cuda_runtime.h>
#include <math.h>

#define N0 8192
#define N1 4096
#define N2 8192
// W0: [N0, N1] row-major, W1: [N1, N2] row-major

// Persistent state (device globals — allocation-free scratch)
__device__ float g_x1[N1];
__device__ float g_x2[N2];
__device__ float g_e1[N1];
__device__ float g_g1[N1];
__device__ float g_g2[N2];
__device__ int   g_ctr;

__device__ __forceinline__ float dot4(float4 a, float4 b) {
    return a.x * b.x + a.y * b.y + a.z * b.z + a.w * b.w;
}

// ---------------------------------------------------------------------------
__global__ void k_init(float* __restrict__ out) {
    int i = blockIdx.x * blockDim.x + threadIdx.x;
    if (i < N1) { g_x1[i] = 0.f; g_g1[i] = 0.f; g_e1[i] = 0.f; }
    if (i < N2) { g_x2[i] = 0.f; g_g2[i] = 0.f; }
    if (i == 0) { out[0] = 0.f; g_ctr = 0; }
}

// ---------------------------------------------------------------------------
// Fused state update by the LAST block (threadfence-reduction pattern).
// float4-vectorized: 4 + 8 iterations for 256 threads. Zeroes grads.
// ---------------------------------------------------------------------------
__device__ __forceinline__ void step_epilogue(int nblocks) {
    __shared__ int is_last;
    __threadfence();
    if (threadIdx.x == 0) {
        int v = atomicAdd(&g_ctr, 1);
        is_last = (v == nblocks - 1);
    }
    __syncthreads();
    if (!is_last) return;
    __threadfence();
    const int tid = threadIdx.x;
    float4* x1v = (float4*)g_x1;
    float4* g1v = (float4*)g_g1;
    float4* e1v = (float4*)g_e1;
    float4* x2v = (float4*)g_x2;
    float4* g2v = (float4*)g_g2;
    const float4 zero = make_float4(0.f, 0.f, 0.f, 0.f);
    #pragma unroll
    for (int it = 0; it < N1 / 4 / 256; it++) {
        int i = tid + it * 256;
        float4 e = e1v[i], g = g1v[i], x = x1v[i];
        x.x = tanhf(x.x + 0.01f * fminf(fmaxf(g.x - e.x, -1.f), 1.f));
        x.y = tanhf(x.y + 0.01f * fminf(fmaxf(g.y - e.y, -1.f), 1.f));
        x.z = tanhf(x.z + 0.01f * fminf(fmaxf(g.z - e.z, -1.f), 1.f));
        x.w = tanhf(x.w + 0.01f * fminf(fmaxf(g.w - e.w, -1.f), 1.f));
        x1v[i] = x;
        g1v[i] = zero;
    }
    #pragma unroll
    for (int it = 0; it < N2 / 4 / 256; it++) {
        int i = tid + it * 256;
        float4 g = g2v[i], x = x2v[i];
        x.x = tanhf(x.x + 0.01f * fminf(fmaxf(g.x - x.x, -1.f), 1.f));
        x.y = tanhf(x.y + 0.01f * fminf(fmaxf(g.y - x.y, -1.f), 1.f));
        x.z = tanhf(x.z + 0.01f * fminf(fmaxf(g.z - x.z, -1.f), 1.f));
        x.w = tanhf(x.w + 0.01f * fminf(fmaxf(g.w - x.w, -1.f), 1.f));
        x2v[i] = x;
        g2v[i] = zero;
    }
    if (tid == 0) g_ctr = 0;
}

// ---------------------------------------------------------------------------
// Step 1 specialized: x1 = x2 = 0  =>  e0 = x0, e1 = 0, g2 = 0.
// Only work: g1 = W0^T x0 (streaming axpy, no barriers) + epilogue.
// grid 256 x 256 thr, 2 blocks/SM: block streams rows [b*32, b*32+32).
// ---------------------------------------------------------------------------
__global__ void __launch_bounds__(256, 2) k_step1(const float* __restrict__ x0,
                                                  const float* __restrict__ W0) {
    const int tid = threadIdx.x;
    const int rowBase = blockIdx.x * 32;
    const float4* Wb = (const float4*)W0;
    float4 acc[4];
    #pragma unroll
    for (int k = 0; k < 4; k++) acc[k] = make_float4(0, 0, 0, 0);

    #pragma unroll 1
    for (int t = 0; t < 16; t++) {
        const int rb = rowBase + t * 2;
        float4 w[8];
        #pragma unroll
        for (int r = 0; r < 2; r++)
            #pragma unroll
            for (int k = 0; k < 4; k++)
                w[4 * r + k] = Wb[(size_t)(rb + r) * 1024 + tid + 256 * k];
        #pragma unroll
        for (int r = 0; r < 2; r++) {
            const float e = __ldg(x0 + rb + r);
            #pragma unroll
            for (int k = 0; k < 4; k++) {
                acc[k].x += e * w[4*r+k].x;  acc[k].y += e * w[4*r+k].y;
                acc[k].z += e * w[4*r+k].z;  acc[k].w += e * w[4*r+k].w;
            }
        }
    }
    #pragma unroll
    for (int k = 0; k < 4; k++) {
        const int c = 4 * (tid + 256 * k);
        atomicAdd(&g_g1[c + 0], acc[k].x);
        atomicAdd(&g_g1[c + 1], acc[k].y);
        atomicAdd(&g_g1[c + 2], acc[k].z);
        atomicAdd(&g_g1[c + 3], acc[k].w);
    }
    step_epilogue(256);
}

// ---------------------------------------------------------------------------
// Steps 2..9: fp32 fused step, 256 threads x 2 blocks/SM (two independent
// barrier domains per SM — block B issues loads while block A reduces).
// Block b: W0 rows [32b,+32) as 16 tiles x 2 rows (4 float4/row/thread),
//          W1 rows [16b,+16) as 16 tiles x 1 row (8 float4/row/thread).
// Live regs ~116 < 128 cap (launch_bounds 256,2): no spill.
// ---------------------------------------------------------------------------
__global__ void __launch_bounds__(256, 2) k_step(const float* __restrict__ x0,
                                                 const float* __restrict__ W0,
                                                 const float* __restrict__ W1) {
    __shared__ float sp[2][8];
    __shared__ float se[2];
    const int tid  = threadIdx.x;
    const int warp = tid >> 5;
    const int lane = tid & 31;

    // ------------------ W0 section: 32 rows ------------------
    {
        const int rowBase = blockIdx.x * 32;
        const float4* Wb = (const float4*)W0;
        const float4* xv = (const float4*)g_x1;
        float4 xA[4];
        #pragma unroll
        for (int k = 0; k < 4; k++) xA[k] = xv[tid + 256 * k];
        float4 acc[4];
        #pragma unroll
        for (int k = 0; k < 4; k++) acc[k] = make_float4(0, 0, 0, 0);

        #pragma unroll 1
        for (int t = 0; t < 16; t++) {
            const int rb = rowBase + t * 2;
            float4 w[8];
            #pragma unroll
            for (int r = 0; r < 2; r++)
                #pragma unroll
                for (int k = 0; k < 4; k++)
                    w[4*r+k] = Wb[(size_t)(rb + r) * 1024 + tid + 256 * k];
            #pragma unroll
            for (int r = 0; r < 2; r++) {
                float p = dot4(w[4*r], xA[0]) + dot4(w[4*r+1], xA[1])
                        + dot4(w[4*r+2], xA[2]) + dot4(w[4*r+3], xA[3]);
                #pragma unroll
                for (int o = 16; o; o >>= 1) p += __shfl_xor_sync(0xFFFFFFFFu, p, o);
                if (lane == 0) sp[r][warp] = p;
            }
            __syncthreads();
            if (tid < 16) {
                const int r = tid >> 3, wi = tid & 7;
                float v = sp[r][wi];
                v += __shfl_xor_sync(0x0000FFFFu, v, 4);
                v += __shfl_xor_sync(0x0000FFFFu, v, 2);
                v += __shfl_xor_sync(0x0000FFFFu, v, 1);
                if (wi == 0) se[r] = __ldg(x0 + rb + r) - tanhf(v);
            }
            __syncthreads();
            #pragma unroll
            for (int r = 0; r < 2; r++) {
                const float e = se[r];
                #pragma unroll
                for (int k = 0; k < 4; k++) {
                    acc[k].x += e * w[4*r+k].x;  acc[k].y += e * w[4*r+k].y;
                    acc[k].z += e * w[4*r+k].z;  acc[k].w += e * w[4*r+k].w;
                }
            }
        }
        #pragma unroll
        for (int k = 0; k < 4; k++) {
            const int c = 4 * (tid + 256 * k);
            atomicAdd(&g_g1[c + 0], acc[k].x);
            atomicAdd(&g_g1[c + 1], acc[k].y);
            atomicAdd(&g_g1[c + 2], acc[k].z);
            atomicAdd(&g_g1[c + 3], acc[k].w);
        }
    }

    // ------------------ W1 section: 16 rows ------------------
    {
        const int rowBase = blockIdx.x * 16;
        const float4* Wb = (const float4*)W1;
        const float4* xv = (const float4*)g_x2;
        float4 xB[8];
        #pragma unroll
        for (int k = 0; k < 8; k++) xB[k] = xv[tid + 256 * k];
        float4 acc[8];
        #pragma unroll
        for (int k = 0; k < 8; k++) acc[k] = make_float4(0, 0, 0, 0);

        #pragma unroll 1
        for (int t = 0; t < 16; t++) {
            const int row = rowBase + t;
            float4 w[8];
            #pragma unroll
            for (int k = 0; k < 8; k++)
                w[k] = Wb[(size_t)row * 2048 + tid + 256 * k];
            float p = 0.f;
            #pragma unroll
            for (int k = 0; k < 8; k++) p += dot4(w[k], xB[k]);
            #pragma unroll
            for (int o = 16; o; o >>= 1) p += __shfl_xor_sync(0xFFFFFFFFu, p, o);
            if (lane == 0) sp[0][warp] = p;
            __syncthreads();
            if (tid < 8) {
                float v = sp[0][tid];
                v += __shfl_xor_sync(0x000000FFu, v, 4);
                v += __shfl_xor_sync(0x000000FFu, v, 2);
                v += __shfl_xor_sync(0x000000FFu, v, 1);
                if (tid == 0) {
                    float e = g_x1[row] - tanhf(v);
                    se[0] = e;
                    g_e1[row] = e;
                }
            }
            __syncthreads();
            const float e = se[0];
            #pragma unroll
            for (int k = 0; k < 8; k++) {
                acc[k].x += e * w[k].x;  acc[k].y += e * w[k].y;
                acc[k].z += e * w[k].z;  acc[k].w += e * w[k].w;
            }
        }
        #pragma unroll
        for (int k = 0; k < 8; k++) {
            const int c = 4 * (tid + 256 * k);
            atomicAdd(&g_g2[c + 0], acc[k].x);
            atomicAdd(&g_g2[c + 1], acc[k].y);
            atomicAdd(&g_g2[c + 2], acc[k].z);
            atomicAdd(&g_g2[c + 3], acc[k].w);
        }
    }

    step_epilogue(256);
}

// ---------------------------------------------------------------------------
// Final: err = ||x0 - tanh(W0@x1)||^2 + ||x1 - tanh(W1@x2)||^2 + ||x2||^2.
// Same 256x2 geometry as k_step, dots only (no axpy/atomics on g).
// Block b: W0 rows [32b,+32), W1 rows [16b,+16), x2 float4 [8b,+8).
// ---------------------------------------------------------------------------
__global__ void __launch_bounds__(256, 2) k_final(const float* __restrict__ x0,
                                                  const float* __restrict__ W0,
                                                  const float* __restrict__ W1,
                                                  float* __restrict__ out) {
    __shared__ float sp[2][8];
    __shared__ float bsum;
    const int tid  = threadIdx.x;
    const int warp = tid >> 5;
    const int lane = tid & 31;
    if (tid == 0) bsum = 0.f;
    __syncthreads();

    // W0 rows -> e0^2
    {
        const int rowBase = blockIdx.x * 32;
        const float4* Wb = (const float4*)W0;
        const float4* xv = (const float4*)g_x1;
        float4 xA[4];
        #pragma unroll
        for (int k = 0; k < 4; k++) xA[k] = xv[tid + 256 * k];

        #pragma unroll 1
        for (int t = 0; t < 16; t++) {
            const int rb = rowBase + t * 2;
            #pragma unroll
            for (int r = 0; r < 2; r++) {
                float4 w0 = Wb[(size_t)(rb + r) * 1024 + tid];
                float4 w1 = Wb[(size_t)(rb + r) * 1024 + tid + 256];
                float4 w2 = Wb[(size_t)(rb + r) * 1024 + tid + 512];
                float4 w3 = Wb[(size_t)(rb + r) * 1024 + tid + 768];
                float p = dot4(w0, xA[0]) + dot4(w1, xA[1])
                        + dot4(w2, xA[2]) + dot4(w3, xA[3]);
                #pragma unroll
                for (int o = 16; o; o >>= 1) p += __shfl_xor_sync(0xFFFFFFFFu, p, o);
                if (lane == 0) sp[r][warp] = p;
            }
            __syncthreads();
            if (tid < 16) {
                const int r = tid >> 3, wi = tid & 7;
                float v = sp[r][wi];
                v += __shfl_xor_sync(0x0000FFFFu, v, 4);
                v += __shfl_xor_sync(0x0000FFFFu, v, 2);
                v += __shfl_xor_sync(0x0000FFFFu, v, 1);
                if (wi == 0) {
                    float e = __ldg(x0 + rb + r) - tanhf(v);
                    atomicAdd(&bsum, e * e);
                }
            }
            __syncthreads();
        }
    }

    // W1 rows -> e1^2
    {
        const int rowBase = blockIdx.x * 16;
        const float4* Wb = (const float4*)W1;
        const float4* xv = (const float4*)g_x2;
        float4 xB[8];
        #pragma unroll
        for (int k = 0; k < 8; k++) xB[k] = xv[tid + 256 * k];

        #pragma unroll 1
        for (int t = 0; t < 16; t++) {
            const int row = rowBase + t;
            float p = 0.f;
            #pragma unroll
            for (int k = 0; k < 8; k++)
                p += dot4(Wb[(size_t)row * 2048 + tid + 256 * k], xB[k]);
            #pragma unroll
            for (int o = 16; o; o >>= 1) p += __shfl_xor_sync(0xFFFFFFFFu, p, o);
            if (lane == 0) sp[0][warp] = p;
            __syncthreads();
            if (tid < 8) {
                float v = sp[0][tid];
                v += __shfl_xor_sync(0x000000FFu, v, 4);
                v += __shfl_xor_sync(0x000000FFu, v, 2);
                v += __shfl_xor_sync(0x000000FFu, v, 1);
                if (tid == 0) {
                    float e = g_x1[row] - tanhf(v);
                    atomicAdd(&bsum, e * e);
                }
            }
            __syncthreads();
        }
    }

    // x2 slice -> ||x2||^2 contribution (2048 float4 / 256 blocks = 8 each)
    if (tid < 8) {
        float4 v = ((const float4*)g_x2)[blockIdx.x * 8 + tid];
        atomicAdd(&bsum, dot4(v, v));
    }

    __syncthreads();
    if (tid == 0) atomicAdd(out, bsum);
}

// ---------------------------------------------------------------------------
extern "C" void kernel_launch(void* const* d_in, const int* in_sizes, int n_in,
                              void* d_out, int out_size) {
    const float* x0 = (const float*)d_in[0];
    const float* W0 = (const float*)d_in[1];
    const float* W1 = (const float*)d_in[2];
    float* out = (float*)d_out;

    k_init<<<32, 256>>>(out);
    k_step1<<<256, 256>>>(x0, W0);                    // specialized step 1
    for (int s = 0; s < 8; s++)
        k_step<<<256, 256>>>(x0, W0, W1);             // fp32 steps 2..9
    k_final<<<256, 256>>>(x0, W0, W1, out);           // final error
}

// round 12
// speedup vs baseline: 1.0112x; 1.0112x over previous
#include <cuda_runtime.h>
#include <math.h>

#define N0 8192
#define N1 4096
#define N2 8192
// W0: [N0, N1] row-major, W1: [N1, N2] row-major

#define GRID 152            // one block per SM on GB300
#define NT0 1024            // W0 tiles: 8 rows x 4096 cols = 128 KB each
#define NT1 1024            // W1 tiles: 4 rows x 8192 cols = 128 KB each

// Persistent state (device globals — allocation-free scratch)
__device__ float g_x1[N1];
__device__ float g_x2[N2];
__device__ float g_e1[N1];
__device__ float g_g1[N1];
__device__ float g_g2[N2];
__device__ int   g_ctr;
__device__ int   g_ctrA;
__device__ int   g_ctrB;

__device__ __forceinline__ float dot4(float4 a, float4 b) {
    return a.x * b.x + a.y * b.y + a.z * b.z + a.w * b.w;
}

// ---------------------------------------------------------------------------
__global__ void k_init(float* __restrict__ out) {
    int i = blockIdx.x * blockDim.x + threadIdx.x;
    if (i < N1) { g_x1[i] = 0.f; g_g1[i] = 0.f; g_e1[i] = 0.f; }
    if (i < N2) { g_x2[i] = 0.f; g_g2[i] = 0.f; }
    if (i == 0) { out[0] = 0.f; g_ctr = 0; g_ctrA = 0; g_ctrB = 0; }
}

// ---------------------------------------------------------------------------
// Fused state update by the LAST block (threadfence-reduction pattern).
// Also resets the work-stealing counters for the next step.
// ---------------------------------------------------------------------------
__device__ __forceinline__ void step_epilogue(int nblocks) {
    __shared__ int is_last;
    __threadfence();
    if (threadIdx.x == 0) {
        int v = atomicAdd(&g_ctr, 1);
        is_last = (v == nblocks - 1);
    }
    __syncthreads();
    if (!is_last) return;
    __threadfence();
    const int tid = threadIdx.x;
    const int nt  = blockDim.x;
    for (int i = tid; i < N1; i += nt) {
        float gr = fminf(fmaxf(-g_e1[i] + g_g1[i], -1.f), 1.f);
        g_x1[i] = tanhf(g_x1[i] + 0.01f * gr);
        g_g1[i] = 0.f;
    }
    for (int i = tid; i < N2; i += nt) {
        float x2 = g_x2[i];
        float gr = fminf(fmaxf(-x2 + g_g2[i], -1.f), 1.f);
        g_x2[i] = tanhf(x2 + 0.01f * gr);
        g_g2[i] = 0.f;
    }
    if (tid == 0) { g_ctr = 0; g_ctrA = 0; g_ctrB = 0; }
}

// ---------------------------------------------------------------------------
// Step 1 specialized: x1 = x2 = 0 => e0 = x0, e1 = 0, g2 = 0.
// Only work: g1 = W0^T x0, work-stolen over 1024 tiles; then epilogue
// (with e1 = 0, g2 = 0 the generic update is exact).
// ---------------------------------------------------------------------------
__global__ void __launch_bounds__(512) k_step1(const float* __restrict__ x0,
                                               const float* __restrict__ W0) {
    __shared__ int sNext;
    const int tid = threadIdx.x;
    const float4* Wb = (const float4*)W0;
    float4 accA = make_float4(0, 0, 0, 0);
    float4 accB = make_float4(0, 0, 0, 0);

    if (tid == 0) sNext = atomicAdd(&g_ctrA, 1);
    __syncthreads();
    int t = sNext;
    while (t < NT0) {
        const int rb = t * 8;
        const float4* base = Wb + (size_t)rb * 1024 + tid;
        float4 wA[8], wB[8];
        #pragma unroll
        for (int r = 0; r < 8; r++) {
            wA[r] = base[(size_t)r * 1024];
            wB[r] = base[(size_t)r * 1024 + 512];
        }
        if (tid == 0) sNext = atomicAdd(&g_ctrA, 1);
        #pragma unroll
        for (int r = 0; r < 8; r++) {
            const float e = __ldg(x0 + rb + r);
            accA.x += e * wA[r].x;  accA.y += e * wA[r].y;
            accA.z += e * wA[r].z;  accA.w += e * wA[r].w;
            accB.x += e * wB[r].x;  accB.y += e * wB[r].y;
            accB.z += e * wB[r].z;  accB.w += e * wB[r].w;
        }
        __syncthreads();
        t = sNext;
    }
    const int cA = 4 * tid;
    const int cB = 4 * (tid + 512);
    atomicAdd(&g_g1[cA + 0], accA.x);
    atomicAdd(&g_g1[cA + 1], accA.y);
    atomicAdd(&g_g1[cA + 2], accA.z);
    atomicAdd(&g_g1[cA + 3], accA.w);
    atomicAdd(&g_g1[cB + 0], accB.x);
    atomicAdd(&g_g1[cB + 1], accB.y);
    atomicAdd(&g_g1[cB + 2], accB.z);
    atomicAdd(&g_g1[cB + 3], accB.w);
    step_epilogue(GRID);
}

// ---------------------------------------------------------------------------
// Steps 2..9: round-3 engine + work stealing. grid 152 x 512 (1 block/SM,
// single wave, perfect balance).
// Phase A: W0 tiles (8 rows, 2 float4/row/thread, 16 LDG.128/tile).
// Phase B: W1 tiles (4 rows, 4 float4/row/thread, 16 LDG.128/tile).
// Column accumulators are tile-order independent; flushed once per phase.
// Tile steal is folded into the post-dot barrier: 2 barriers/tile.
// ---------------------------------------------------------------------------
__global__ void __launch_bounds__(512) k_step(const float* __restrict__ x0,
                                              const float* __restrict__ W0,
                                              const float* __restrict__ W1) {
    __shared__ float sp[8][16];
    __shared__ float se[8];
    __shared__ int sNext;
    const int tid  = threadIdx.x;
    const int warp = tid >> 5;
    const int lane = tid & 31;

    // ------------------ Phase A: W0 tiles ------------------
    {
        const float4* Wb = (const float4*)W0;
        const float4* xv = (const float4*)g_x1;
        const float4 xA = xv[tid];
        const float4 xB = xv[tid + 512];
        float4 accA = make_float4(0, 0, 0, 0);
        float4 accB = make_float4(0, 0, 0, 0);

        if (tid == 0) sNext = atomicAdd(&g_ctrA, 1);
        __syncthreads();
        int t = sNext;
        while (t < NT0) {
            const int rb = t * 8;
            const float4* base = Wb + (size_t)rb * 1024 + tid;
            float4 wA[8], wB[8];
            #pragma unroll
            for (int r = 0; r < 8; r++) {
                wA[r] = base[(size_t)r * 1024];
                wB[r] = base[(size_t)r * 1024 + 512];
            }
            #pragma unroll
            for (int r = 0; r < 8; r++) {
                float p = dot4(wA[r], xA) + dot4(wB[r], xB);
                #pragma unroll
                for (int o = 16; o; o >>= 1) p += __shfl_xor_sync(0xFFFFFFFFu, p, o);
                if (lane == 0) sp[r][warp] = p;
            }
            if (tid == 0) sNext = atomicAdd(&g_ctrA, 1);
            __syncthreads();      // sp ready + sNext published
            if (tid < 128) {
                const int r = tid >> 4, wi = tid & 15;
                float v = sp[r][wi];
                v += __shfl_xor_sync(0xFFFFFFFFu, v, 8);
                v += __shfl_xor_sync(0xFFFFFFFFu, v, 4);
                v += __shfl_xor_sync(0xFFFFFFFFu, v, 2);
                v += __shfl_xor_sync(0xFFFFFFFFu, v, 1);
                if (wi == 0) se[r] = __ldg(x0 + rb + r) - tanhf(v);
            }
            __syncthreads();
            #pragma unroll
            for (int r = 0; r < 8; r++) {
                const float e = se[r];
                accA.x += e * wA[r].x;  accA.y += e * wA[r].y;
                accA.z += e * wA[r].z;  accA.w += e * wA[r].w;
                accB.x += e * wB[r].x;  accB.y += e * wB[r].y;
                accB.z += e * wB[r].z;  accB.w += e * wB[r].w;
            }
            t = sNext;
        }
        const int cA = 4 * tid;
        const int cB = 4 * (tid + 512);
        atomicAdd(&g_g1[cA + 0], accA.x);
        atomicAdd(&g_g1[cA + 1], accA.y);
        atomicAdd(&g_g1[cA + 2], accA.z);
        atomicAdd(&g_g1[cA + 3], accA.w);
        atomicAdd(&g_g1[cB + 0], accB.x);
        atomicAdd(&g_g1[cB + 1], accB.y);
        atomicAdd(&g_g1[cB + 2], accB.z);
        atomicAdd(&g_g1[cB + 3], accB.w);
    }

    // ------------------ Phase B: W1 tiles ------------------
    {
        const float4* Wb = (const float4*)W1;
        const float4* xv = (const float4*)g_x2;
        float4 xC[4];
        #pragma unroll
        for (int k = 0; k < 4; k++) xC[k] = xv[tid + k * 512];
        float4 acc[4] = {make_float4(0,0,0,0), make_float4(0,0,0,0),
                         make_float4(0,0,0,0), make_float4(0,0,0,0)};

        if (tid == 0) sNext = atomicAdd(&g_ctrB, 1);
        __syncthreads();
        int t = sNext;
        while (t < NT1) {
            const int rb = t * 4;
            const float4* base = Wb + (size_t)rb * 2048 + tid;
            float4 w[4][4];
            #pragma unroll
            for (int r = 0; r < 4; r++)
                #pragma unroll
                for (int k = 0; k < 4; k++)
                    w[r][k] = base[(size_t)r * 2048 + k * 512];
            #pragma unroll
            for (int r = 0; r < 4; r++) {
                float p = dot4(w[r][0], xC[0]) + dot4(w[r][1], xC[1])
                        + dot4(w[r][2], xC[2]) + dot4(w[r][3], xC[3]);
                #pragma unroll
                for (int o = 16; o; o >>= 1) p += __shfl_xor_sync(0xFFFFFFFFu, p, o);
                if (lane == 0) sp[r][warp] = p;
            }
            if (tid == 0) sNext = atomicAdd(&g_ctrB, 1);
            __syncthreads();
            if (tid < 64) {
                const int r = tid >> 4, wi = tid & 15;
                float v = sp[r][wi];
                v += __shfl_xor_sync(0xFFFFFFFFu, v, 8);
                v += __shfl_xor_sync(0xFFFFFFFFu, v, 4);
                v += __shfl_xor_sync(0xFFFFFFFFu, v, 2);
                v += __shfl_xor_sync(0xFFFFFFFFu, v, 1);
                if (wi == 0) {
                    float e = g_x1[rb + r] - tanhf(v);
                    se[r] = e;
                    g_e1[rb + r] = e;
                }
            }
            __syncthreads();
            #pragma unroll
            for (int r = 0; r < 4; r++) {
                const float e = se[r];
                #pragma unroll
                for (int k = 0; k < 4; k++) {
                    acc[k].x += e * w[r][k].x;  acc[k].y += e * w[r][k].y;
                    acc[k].z += e * w[r][k].z;  acc[k].w += e * w[r][k].w;
                }
            }
            t = sNext;
        }
        #pragma unroll
        for (int k = 0; k < 4; k++) {
            const int c = 4 * (tid + k * 512);
            atomicAdd(&g_g2[c + 0], acc[k].x);
            atomicAdd(&g_g2[c + 1], acc[k].y);
            atomicAdd(&g_g2[c + 2], acc[k].z);
            atomicAdd(&g_g2[c + 3], acc[k].w);
        }
    }

    step_epilogue(GRID);
}

// ---------------------------------------------------------------------------
// Final: err = ||x0 - tanh(W0@x1)||^2 + ||x1 - tanh(W1@x2)||^2 + ||x2||^2.
// Work-stolen dots only (no axpy). Block 0 adds ||x2||^2.
// Counters are 0 on entry (reset by the last step's epilogue).
// ---------------------------------------------------------------------------
__global__ void __launch_bounds__(512) k_final(const float* __restrict__ x0,
                                               const float* __restrict__ W0,
                                               const float* __restrict__ W1,
                                               float* __restrict__ out) {
    __shared__ float sp[8][16];
    __shared__ float bsum;
    __shared__ int sNext;
    const int tid  = threadIdx.x;
    const int warp = tid >> 5;
    const int lane = tid & 31;
    if (tid == 0) bsum = 0.f;

    // ---- W0 tiles: e0^2 ----
    {
        const float4* Wb = (const float4*)W0;
        const float4* xv = (const float4*)g_x1;
        const float4 xA = xv[tid];
        const float4 xB = xv[tid + 512];

        if (tid == 0) sNext = atomicAdd(&g_ctrA, 1);
        __syncthreads();
        int t = sNext;
        while (t < NT0) {
            const int rb = t * 8;
            const float4* base = Wb + (size_t)rb * 1024 + tid;
            #pragma unroll
            for (int r = 0; r < 8; r++) {
                float4 wA = base[(size_t)r * 1024];
                float4 wB = base[(size_t)r * 1024 + 512];
                float p = dot4(wA, xA) + dot4(wB, xB);
                #pragma unroll
                for (int o = 16; o; o >>= 1) p += __shfl_xor_sync(0xFFFFFFFFu, p, o);
                if (lane == 0) sp[r][warp] = p;
            }
            if (tid == 0) sNext = atomicAdd(&g_ctrA, 1);
            __syncthreads();
            if (tid < 128) {
                const int r = tid >> 4, wi = tid & 15;
                float v = sp[r][wi];
                v += __shfl_xor_sync(0xFFFFFFFFu, v, 8);
                v += __shfl_xor_sync(0xFFFFFFFFu, v, 4);
                v += __shfl_xor_sync(0xFFFFFFFFu, v, 2);
                v += __shfl_xor_sync(0xFFFFFFFFu, v, 1);
                if (wi == 0) {
                    float e = __ldg(x0 + rb + r) - tanhf(v);
                    atomicAdd(&bsum, e * e);
                }
            }
            __syncthreads();
            t = sNext;
        }
    }

    // ---- W1 tiles: e1^2 ----
    {
        const float4* Wb = (const float4*)W1;
        const float4* xv = (const float4*)g_x2;
        float4 xC[4];
        #pragma unroll
        for (int k = 0; k < 4; k++) xC[k] = xv[tid + k * 512];

        if (tid == 0) sNext = atomicAdd(&g_ctrB, 1);
        __syncthreads();
        int t = sNext;
        while (t < NT1) {
            const int rb = t * 4;
            const float4* base = Wb + (size_t)rb * 2048 + tid;
            #pragma unroll
            for (int r = 0; r < 4; r++) {
                float p = 0.f;
                #pragma unroll
                for (int k = 0; k < 4; k++)
                    p += dot4(base[(size_t)r * 2048 + k * 512], xC[k]);
                #pragma unroll
                for (int o = 16; o; o >>= 1) p += __shfl_xor_sync(0xFFFFFFFFu, p, o);
                if (lane == 0) sp[r][warp] = p;
            }
            if (tid == 0) sNext = atomicAdd(&g_ctrB, 1);
            __syncthreads();
            if (tid < 64) {
                const int r = tid >> 4, wi = tid & 15;
                float v = sp[r][wi];
                v += __shfl_xor_sync(0xFFFFFFFFu, v, 8);
                v += __shfl_xor_sync(0xFFFFFFFFu, v, 4);
                v += __shfl_xor_sync(0xFFFFFFFFu, v, 2);
                v += __shfl_xor_sync(0xFFFFFFFFu, v, 1);
                if (wi == 0) {
                    float e = g_x1[rb + r] - tanhf(v);
                    atomicAdd(&bsum, e * e);
                }
            }
            __syncthreads();
            t = sNext;
        }
    }

    // ---- ||x2||^2 (block 0 only: 2048 float4 / 512 thr = 4 each) ----
    if (blockIdx.x == 0) {
        const float4* xv = (const float4*)g_x2;
        float s = 0.f;
        #pragma unroll
        for (int k = 0; k < 4; k++) {
            float4 v = xv[tid + k * 512];
            s += dot4(v, v);
        }
        #pragma unroll
        for (int o = 16; o; o >>= 1) s += __shfl_xor_sync(0xFFFFFFFFu, s, o);
        if (lane == 0) atomicAdd(&bsum, s);
    }

    __syncthreads();
    if (tid == 0) atomicAdd(out, bsum);
}

// ---------------------------------------------------------------------------
extern "C" void kernel_launch(void* const* d_in, const int* in_sizes, int n_in,
                              void* d_out, int out_size) {
    const float* x0 = (const float*)d_in[0];
    const float* W0 = (const float*)d_in[1];
    const float* W1 = (const float*)d_in[2];
    float* out = (float*)d_out;

    k_init<<<32, 256>>>(out);
    k_step1<<<GRID, 512>>>(x0, W0);                    // specialized step 1
    for (int s = 0; s < 8; s++)
        k_step<<<GRID, 512>>>(x0, W0, W1);             // fp32 steps 2..9
    k_final<<<GRID, 512>>>(x0, W0, W1, out);           // final error
}

// round 13
// speedup vs baseline: 1.1718x; 1.1588x over previous
#include <cuda_runtime.h>
#include <math.h>

#define N0 8192
#define N1 4096
#define N2 8192
// W0: [N0, N1] row-major, W1: [N1, N2] row-major

// Persistent state (device globals — allocation-free scratch)
__device__ float g_x1[N1];
__device__ float g_x2[N2];
__device__ float g_e1[N1];
__device__ float g_g1[N1];
__device__ float g_g2[N2];
__device__ int   g_ctr;

__device__ __forceinline__ float dot4(float4 a, float4 b) {
    return a.x * b.x + a.y * b.y + a.z * b.z + a.w * b.w;
}

// ---------------------------------------------------------------------------
__global__ void k_init(float* __restrict__ out) {
    int i = blockIdx.x * blockDim.x + threadIdx.x;
    if (i < N1) { g_x1[i] = 0.f; g_g1[i] = 0.f; g_e1[i] = 0.f; }
    if (i < N2) { g_x2[i] = 0.f; g_g2[i] = 0.f; }
    if (i == 0) { out[0] = 0.f; g_ctr = 0; }
}

// ---------------------------------------------------------------------------
// Fused state update by the LAST block (threadfence-reduction pattern).
// x1 <- tanh(x1 + .01 clip(g1 - e1)); x2 <- tanh(x2 + .01 clip(g2 - x2)).
// Zeroes grads, resets counter.
// ---------------------------------------------------------------------------
__device__ __forceinline__ void step_epilogue(int nblocks) {
    __shared__ int is_last;
    __threadfence();
    if (threadIdx.x == 0) {
        int v = atomicAdd(&g_ctr, 1);
        is_last = (v == nblocks - 1);
    }
    __syncthreads();
    if (!is_last) return;
    __threadfence();
    const int tid = threadIdx.x;
    const int nt  = blockDim.x;
    for (int i = tid; i < N1; i += nt) {
        float gr = fminf(fmaxf(-g_e1[i] + g_g1[i], -1.f), 1.f);
        g_x1[i] = tanhf(g_x1[i] + 0.01f * gr);
        g_g1[i] = 0.f;
    }
    for (int i = tid; i < N2; i += nt) {
        float x2 = g_x2[i];
        float gr = fminf(fmaxf(-x2 + g_g2[i], -1.f), 1.f);
        g_x2[i] = tanhf(x2 + 0.01f * gr);
        g_g2[i] = 0.f;
    }
    if (tid == 0) g_ctr = 0;
}

// ---------------------------------------------------------------------------
// Step 1 specialized: x1 = x2 = 0 => e0 = x0, e1 = 0, g2 = 0.
// Only work: g1 = W0^T x0 (streaming axpy, no dots, no per-tile barriers),
// then the generic epilogue (e1 = 0, g2 = 0 make the update exact).
// grid 256 x 512: block streams W0 rows [b*32, b*32+32) as 4 tiles x 8 rows.
// ---------------------------------------------------------------------------
__global__ void __launch_bounds__(512) k_step1(const float* __restrict__ x0,
                                               const float* __restrict__ W0) {
    const int tid = threadIdx.x;
    const int rowBase = blockIdx.x * 32;
    const float4* Wb = (const float4*)W0;
    float4 accA = make_float4(0, 0, 0, 0);
    float4 accB = make_float4(0, 0, 0, 0);

    #pragma unroll 1
    for (int t = 0; t < 4; t++) {
        const int rb = rowBase + t * 8;
        const float4* base = Wb + (size_t)rb * 1024 + tid;
        float4 wA[8], wB[8];
        #pragma unroll
        for (int r = 0; r < 8; r++) {
            wA[r] = base[(size_t)r * 1024];
            wB[r] = base[(size_t)r * 1024 + 512];
        }
        #pragma unroll
        for (int r = 0; r < 8; r++) {
            const float e = __ldg(x0 + rb + r);
            accA.x += e * wA[r].x;  accA.y += e * wA[r].y;
            accA.z += e * wA[r].z;  accA.w += e * wA[r].w;
            accB.x += e * wB[r].x;  accB.y += e * wB[r].y;
            accB.z += e * wB[r].z;  accB.w += e * wB[r].w;
        }
    }
    const int cA = 4 * tid;
    const int cB = 4 * (tid + 512);
    atomicAdd(&g_g1[cA + 0], accA.x);
    atomicAdd(&g_g1[cA + 1], accA.y);
    atomicAdd(&g_g1[cA + 2], accA.z);
    atomicAdd(&g_g1[cA + 3], accA.w);
    atomicAdd(&g_g1[cB + 0], accB.x);
    atomicAdd(&g_g1[cB + 1], accB.y);
    atomicAdd(&g_g1[cB + 2], accB.z);
    atomicAdd(&g_g1[cB + 3], accB.w);
    step_epilogue(256);
}

// ---------------------------------------------------------------------------
// Steps 2..9: the ROUND-3 engine, verbatim, + fused epilogue.
// Blocks [0,128): W0, 64 rows each (8 tiles x 8 rows, 2 float4/row/thread).
// Blocks [128,256): W1, 32 rows each (8 tiles x 4 rows, 4 float4/row/thread).
// 16 back-to-back LDG.128 per tile; 2 barriers per tile; register-resident
// weights reused for the rank-k update; one atomic flush per block.
// ---------------------------------------------------------------------------
__global__ void __launch_bounds__(512) k_step(const float* __restrict__ x0,
                                              const float* __restrict__ W0,
                                              const float* __restrict__ W1) {
    __shared__ float sp[8][16];
    __shared__ float se[8];
    const int tid  = threadIdx.x;
    const int warp = tid >> 5;
    const int lane = tid & 31;

    if (blockIdx.x < 128) {
        // ---------------- W0 half: [8192 x 4096] ----------------
        const int rowBase = blockIdx.x * 64;
        const float4* xv = (const float4*)g_x1;
        const float4 xA = xv[tid];
        const float4 xB = xv[tid + 512];
        float4 accA = make_float4(0, 0, 0, 0);
        float4 accB = make_float4(0, 0, 0, 0);

        #pragma unroll 1
        for (int t = 0; t < 8; t++) {
            const int rb = rowBase + t * 8;
            const float4* base = (const float4*)W0 + (size_t)rb * 1024 + tid;

            float4 wA[8], wB[8];
            #pragma unroll
            for (int r = 0; r < 8; r++) {
                wA[r] = base[(size_t)r * 1024];
                wB[r] = base[(size_t)r * 1024 + 512];
            }
            #pragma unroll
            for (int r = 0; r < 8; r++) {
                float p = dot4(wA[r], xA) + dot4(wB[r], xB);
                #pragma unroll
                for (int o = 16; o; o >>= 1) p += __shfl_xor_sync(0xFFFFFFFFu, p, o);
                if (lane == 0) sp[r][warp] = p;
            }
            __syncthreads();
            if (tid < 8) {
                float s = 0.f;
                #pragma unroll
                for (int w = 0; w < 16; w++) s += sp[tid][w];
                se[tid] = x0[rb + tid] - tanhf(s);
            }
            __syncthreads();
            #pragma unroll
            for (int r = 0; r < 8; r++) {
                const float e = se[r];
                accA.x += e * wA[r].x;  accA.y += e * wA[r].y;
                accA.z += e * wA[r].z;  accA.w += e * wA[r].w;
                accB.x += e * wB[r].x;  accB.y += e * wB[r].y;
                accB.z += e * wB[r].z;  accB.w += e * wB[r].w;
            }
        }
        const int cA = 4 * tid;
        const int cB = 4 * (tid + 512);
        atomicAdd(&g_g1[cA + 0], accA.x);
        atomicAdd(&g_g1[cA + 1], accA.y);
        atomicAdd(&g_g1[cA + 2], accA.z);
        atomicAdd(&g_g1[cA + 3], accA.w);
        atomicAdd(&g_g1[cB + 0], accB.x);
        atomicAdd(&g_g1[cB + 1], accB.y);
        atomicAdd(&g_g1[cB + 2], accB.z);
        atomicAdd(&g_g1[cB + 3], accB.w);
    } else {
        // ---------------- W1 half: [4096 x 8192] ----------------
        const int rowBase = (blockIdx.x - 128) * 32;
        const float4* xv = (const float4*)g_x2;
        float4 xC[4];
        #pragma unroll
        for (int k = 0; k < 4; k++) xC[k] = xv[tid + k * 512];
        float4 acc[4] = {make_float4(0,0,0,0), make_float4(0,0,0,0),
                         make_float4(0,0,0,0), make_float4(0,0,0,0)};

        #pragma unroll 1
        for (int t = 0; t < 8; t++) {
            const int rb = rowBase + t * 4;
            const float4* base = (const float4*)W1 + (size_t)rb * 2048 + tid;

            float4 w[4][4];
            #pragma unroll
            for (int r = 0; r < 4; r++)
                #pragma unroll
                for (int k = 0; k < 4; k++)
                    w[r][k] = base[(size_t)r * 2048 + k * 512];

            #pragma unroll
            for (int r = 0; r < 4; r++) {
                float p = dot4(w[r][0], xC[0]) + dot4(w[r][1], xC[1])
                        + dot4(w[r][2], xC[2]) + dot4(w[r][3], xC[3]);
                #pragma unroll
                for (int o = 16; o; o >>= 1) p += __shfl_xor_sync(0xFFFFFFFFu, p, o);
                if (lane == 0) sp[r][warp] = p;
            }
            __syncthreads();
            if (tid < 4) {
                float s = 0.f;
                #pragma unroll
                for (int wi = 0; wi < 16; wi++) s += sp[tid][wi];
                float e = g_x1[rb + tid] - tanhf(s);
                se[tid] = e;
                g_e1[rb + tid] = e;
            }
            __syncthreads();
            #pragma unroll
            for (int r = 0; r < 4; r++) {
                const float e = se[r];
                #pragma unroll
                for (int k = 0; k < 4; k++) {
                    acc[k].x += e * w[r][k].x;  acc[k].y += e * w[r][k].y;
                    acc[k].z += e * w[r][k].z;  acc[k].w += e * w[r][k].w;
                }
            }
        }
        #pragma unroll
        for (int k = 0; k < 4; k++) {
            const int c = 4 * (tid + k * 512);
            atomicAdd(&g_g2[c + 0], acc[k].x);
            atomicAdd(&g_g2[c + 1], acc[k].y);
            atomicAdd(&g_g2[c + 2], acc[k].z);
            atomicAdd(&g_g2[c + 3], acc[k].w);
        }
    }
    step_epilogue(256);
}

// ---------------------------------------------------------------------------
// Final step (round-3 verbatim):
// err = ||x0 - tanh(W0@x1)||^2 + ||x1 - tanh(W1@x2)||^2 + ||x2||^2
// Warp-per-row; W0 rows fold in x2[j]^2 (N2 == N0).
// ---------------------------------------------------------------------------
__global__ void __launch_bounds__(256) k_final(const float* __restrict__ x0,
                                               const float* __restrict__ W0,
                                               const float* __restrict__ W1,
                                               float* __restrict__ out) {
    __shared__ float s_part[8];
    int warpInBlock = threadIdx.x >> 5;
    int warp = (blockIdx.x * blockDim.x + threadIdx.x) >> 5;
    int lane = threadIdx.x & 31;

    float local = 0.f;
    if (warp < N0) {
        const float4* row = (const float4*)(W0 + (size_t)warp * N1);
        const float4* xv  = (const float4*)g_x1;
        float acc = 0.f;
        #pragma unroll 4
        for (int i = lane; i < N1 / 4; i += 32) acc += dot4(row[i], xv[i]);
        #pragma unroll
        for (int o = 16; o; o >>= 1) acc += __shfl_xor_sync(0xFFFFFFFFu, acc, o);
        if (lane == 0) {
            float e = x0[warp] - tanhf(acc);
            float x2v = g_x2[warp];
            local = e * e + x2v * x2v;
        }
    } else {
        int r = warp - N0;
        const float4* row = (const float4*)(W1 + (size_t)r * N2);
        const float4* xv  = (const float4*)g_x2;
        float acc = 0.f;
        #pragma unroll 4
        for (int i = lane; i < N2 / 4; i += 32) acc += dot4(row[i], xv[i]);
        #pragma unroll
        for (int o = 16; o; o >>= 1) acc += __shfl_xor_sync(0xFFFFFFFFu, acc, o);
        if (lane == 0) {
            float e = g_x1[r] - tanhf(acc);
            local = e * e;
        }
    }

    if (lane == 0) s_part[warpInBlock] = local;
    __syncthreads();
    if (threadIdx.x == 0) {
        float s = 0.f;
        #pragma unroll
        for (int w = 0; w < 8; w++) s += s_part[w];
        atomicAdd(out, s);
    }
}

// ---------------------------------------------------------------------------
extern "C" void kernel_launch(void* const* d_in, const int* in_sizes, int n_in,
                              void* d_out, int out_size) {
    const float* x0 = (const float*)d_in[0];
    const float* W0 = (const float*)d_in[1];
    const float* W1 = (const float*)d_in[2];
    float* out = (float*)d_out;

    k_init<<<32, 256>>>(out);
    k_step1<<<256, 512>>>(x0, W0);                    // specialized step 1
    for (int s = 0; s < 8; s++)
        k_step<<<256, 512>>>(x0, W0, W1);             // round-3 engine + epilogue
    k_final<<<(N0 + N1) / 8, 256>>>(x0, W0, W1, out); // final error
}

// round 14
// speedup vs baseline: 1.4504x; 1.2377x over previous
#include <cuda_runtime.h>
#include <math.h>

#define N0 8192
#define N1 4096
#define N2 8192
// W0: [N0, N1] row-major, W1: [N1, N2] row-major

// Persistent state (device globals — allocation-free scratch)
__device__ float g_x1[N1];
__device__ float g_x2[N2];
__device__ float g_e1[N1];
__device__ float g_g1[N1];
__device__ float g_g2[N2];

__device__ __forceinline__ float dot4(float4 a, float4 b) {
    return a.x * b.x + a.y * b.y + a.z * b.z + a.w * b.w;
}

// ---------------------------------------------------------------------------
__global__ void k_init(float* __restrict__ out) {
    int i = blockIdx.x * blockDim.x + threadIdx.x;
    if (i < N1) { g_x1[i] = 0.f; g_g1[i] = 0.f; g_e1[i] = 0.f; }
    if (i < N2) { g_x2[i] = 0.f; g_g2[i] = 0.f; }
    if (i == 0) out[0] = 0.f;
}

// ---------------------------------------------------------------------------
// Step 1 specialized: x1 = x2 = 0 => e0 = x0, e1 = 0, g2 = 0.
// Only work: g1 = W0^T x0 (streaming axpy, no dots, no barriers).
// The following k_update (with e1 = 0, g2 = 0) applies the exact update.
// grid 256 x 512: block streams W0 rows [b*32, b*32+32) as 4 tiles x 8 rows.
// ---------------------------------------------------------------------------
__global__ void __launch_bounds__(512) k_step1(const float* __restrict__ x0,
                                               const float* __restrict__ W0) {
    const int tid = threadIdx.x;
    const int rowBase = blockIdx.x * 32;
    const float4* Wb = (const float4*)W0;
    float4 accA = make_float4(0, 0, 0, 0);
    float4 accB = make_float4(0, 0, 0, 0);

    #pragma unroll 1
    for (int t = 0; t < 4; t++) {
        const int rb = rowBase + t * 8;
        const float4* base = Wb + (size_t)rb * 1024 + tid;
        float4 wA[8], wB[8];
        #pragma unroll
        for (int r = 0; r < 8; r++) {
            wA[r] = base[(size_t)r * 1024];
            wB[r] = base[(size_t)r * 1024 + 512];
        }
        #pragma unroll
        for (int r = 0; r < 8; r++) {
            const float e = __ldg(x0 + rb + r);
            accA.x += e * wA[r].x;  accA.y += e * wA[r].y;
            accA.z += e * wA[r].z;  accA.w += e * wA[r].w;
            accB.x += e * wB[r].x;  accB.y += e * wB[r].y;
            accB.z += e * wB[r].z;  accB.w += e * wB[r].w;
        }
    }
    const int cA = 4 * tid;
    const int cB = 4 * (tid + 512);
    atomicAdd(&g_g1[cA + 0], accA.x);
    atomicAdd(&g_g1[cA + 1], accA.y);
    atomicAdd(&g_g1[cA + 2], accA.z);
    atomicAdd(&g_g1[cA + 3], accA.w);
    atomicAdd(&g_g1[cB + 0], accB.x);
    atomicAdd(&g_g1[cB + 1], accB.y);
    atomicAdd(&g_g1[cB + 2], accB.z);
    atomicAdd(&g_g1[cB + 3], accB.w);
}

// ---------------------------------------------------------------------------
// Fused step (ROUND-3 ENGINE, VERBATIM): one DRAM pass over each weight
// matrix computes both e and the transposed accumulation.
// Blocks [0,128): W0, 64 rows each (8 tiles x 8 rows, 2 float4/row/thread).
// Blocks [128,256): W1, 32 rows each (8 tiles x 4 rows, 4 float4/row/thread).
// ---------------------------------------------------------------------------
__global__ void __launch_bounds__(512) k_step(const float* __restrict__ x0,
                                              const float* __restrict__ W0,
                                              const float* __restrict__ W1) {
    __shared__ float sp[8][16];
    __shared__ float se[8];
    const int tid  = threadIdx.x;
    const int warp = tid >> 5;
    const int lane = tid & 31;

    if (blockIdx.x < 128) {
        // ---------------- W0 half: [8192 x 4096] ----------------
        const int rowBase = blockIdx.x * 64;
        const float4* xv = (const float4*)g_x1;          // 1024 float4
        const float4 xA = xv[tid];
        const float4 xB = xv[tid + 512];
        float4 accA = make_float4(0,0,0,0);
        float4 accB = make_float4(0,0,0,0);

        #pragma unroll 1
        for (int t = 0; t < 8; t++) {
            const int rb = rowBase + t * 8;
            const float4* base = (const float4*)W0 + (size_t)rb * 1024 + tid;

            float4 wA[8], wB[8];
            #pragma unroll
            for (int r = 0; r < 8; r++) {
                wA[r] = base[(size_t)r * 1024];
                wB[r] = base[(size_t)r * 1024 + 512];
            }
            // partial dots + warp reduce
            #pragma unroll
            for (int r = 0; r < 8; r++) {
                float p = dot4(wA[r], xA) + dot4(wB[r], xB);
                #pragma unroll
                for (int o = 16; o; o >>= 1) p += __shfl_xor_sync(0xFFFFFFFFu, p, o);
                if (lane == 0) sp[r][warp] = p;
            }
            __syncthreads();
            if (tid < 8) {
                float s = 0.f;
                #pragma unroll
                for (int w = 0; w < 16; w++) s += sp[tid][w];
                se[tid] = x0[rb + tid] - tanhf(s);
            }
            __syncthreads();
            // rank-8 update from registers
            #pragma unroll
            for (int r = 0; r < 8; r++) {
                const float e = se[r];
                accA.x += e * wA[r].x;  accA.y += e * wA[r].y;
                accA.z += e * wA[r].z;  accA.w += e * wA[r].w;
                accB.x += e * wB[r].x;  accB.y += e * wB[r].y;
                accB.z += e * wB[r].z;  accB.w += e * wB[r].w;
            }
        }
        const int cA = 4 * tid;
        const int cB = 4 * (tid + 512);
        atomicAdd(&g_g1[cA + 0], accA.x);
        atomicAdd(&g_g1[cA + 1], accA.y);
        atomicAdd(&g_g1[cA + 2], accA.z);
        atomicAdd(&g_g1[cA + 3], accA.w);
        atomicAdd(&g_g1[cB + 0], accB.x);
        atomicAdd(&g_g1[cB + 1], accB.y);
        atomicAdd(&g_g1[cB + 2], accB.z);
        atomicAdd(&g_g1[cB + 3], accB.w);
    } else {
        // ---------------- W1 half: [4096 x 8192] ----------------
        const int rowBase = (blockIdx.x - 128) * 32;
        const float4* xv = (const float4*)g_x2;          // 2048 float4
        float4 xC[4];
        #pragma unroll
        for (int k = 0; k < 4; k++) xC[k] = xv[tid + k * 512];
        float4 acc[4] = {make_float4(0,0,0,0), make_float4(0,0,0,0),
                         make_float4(0,0,0,0), make_float4(0,0,0,0)};

        #pragma unroll 1
        for (int t = 0; t < 8; t++) {
            const int rb = rowBase + t * 4;
            const float4* base = (const float4*)W1 + (size_t)rb * 2048 + tid;

            float4 w[4][4];
            #pragma unroll
            for (int r = 0; r < 4; r++)
                #pragma unroll
                for (int k = 0; k < 4; k++)
                    w[r][k] = base[(size_t)r * 2048 + k * 512];

            #pragma unroll
            for (int r = 0; r < 4; r++) {
                float p = dot4(w[r][0], xC[0]) + dot4(w[r][1], xC[1])
                        + dot4(w[r][2], xC[2]) + dot4(w[r][3], xC[3]);
                #pragma unroll
                for (int o = 16; o; o >>= 1) p += __shfl_xor_sync(0xFFFFFFFFu, p, o);
                if (lane == 0) sp[r][warp] = p;
            }
            __syncthreads();
            if (tid < 4) {
                float s = 0.f;
                #pragma unroll
                for (int wi = 0; wi < 16; wi++) s += sp[tid][wi];
                float e = g_x1[rb + tid] - tanhf(s);
                se[tid] = e;
                g_e1[rb + tid] = e;
            }
            __syncthreads();
            #pragma unroll
            for (int r = 0; r < 4; r++) {
                const float e = se[r];
                #pragma unroll
                for (int k = 0; k < 4; k++) {
                    acc[k].x += e * w[r][k].x;  acc[k].y += e * w[r][k].y;
                    acc[k].z += e * w[r][k].z;  acc[k].w += e * w[r][k].w;
                }
            }
        }
        #pragma unroll
        for (int k = 0; k < 4; k++) {
            const int c = 4 * (tid + k * 512);
            atomicAdd(&g_g2[c + 0], acc[k].x);
            atomicAdd(&g_g2[c + 1], acc[k].y);
            atomicAdd(&g_g2[c + 2], acc[k].z);
            atomicAdd(&g_g2[c + 3], acc[k].w);
        }
    }
}

// ---------------------------------------------------------------------------
// State update (separate kernel — measured 4.8 us at this geometry, beats
// the single-block fused epilogue by ~12 us/step). Zeroes grads for reuse.
// ---------------------------------------------------------------------------
__global__ void k_update() {
    int i = blockIdx.x * blockDim.x + threadIdx.x;
    if (i < N1) {
        float gr = fminf(fmaxf(-g_e1[i] + g_g1[i], -1.f), 1.f);
        g_x1[i] = tanhf(g_x1[i] + 0.01f * gr);
        g_g1[i] = 0.f;
    } else {
        int c = i - N1;
        float x2 = g_x2[c];
        float gr = fminf(fmaxf(-x2 + g_g2[c], -1.f), 1.f);
        g_x2[c] = tanhf(x2 + 0.01f * gr);
        g_g2[c] = 0.f;
    }
}

// ---------------------------------------------------------------------------
// Final step (round-3 verbatim):
// err = ||x0 - tanh(W0@x1)||^2 + ||x1 - tanh(W1@x2)||^2 + ||x2||^2
// Warp-per-row; W0 rows fold in x2[j]^2 (N2 == N0).
// ---------------------------------------------------------------------------
__global__ void k_final(const float* __restrict__ x0,
                        const float* __restrict__ W0,
                        const float* __restrict__ W1,
                        float* __restrict__ out) {
    __shared__ float s_part[8];
    int warpInBlock = threadIdx.x >> 5;
    int warp = (blockIdx.x * blockDim.x + threadIdx.x) >> 5;
    int lane = threadIdx.x & 31;

    float local = 0.f;
    if (warp < N0) {
        const float4* row = (const float4*)(W0 + (size_t)warp * N1);
        const float4* xv  = (const float4*)g_x1;
        float acc = 0.f;
        #pragma unroll 4
        for (int i = lane; i < N1 / 4; i += 32) acc += dot4(row[i], xv[i]);
        #pragma unroll
        for (int o = 16; o; o >>= 1) acc += __shfl_xor_sync(0xFFFFFFFFu, acc, o);
        if (lane == 0) {
            float e = x0[warp] - tanhf(acc);
            float x2v = g_x2[warp];
            local = e * e + x2v * x2v;
        }
    } else {
        int r = warp - N0;
        const float4* row = (const float4*)(W1 + (size_t)r * N2);
        const float4* xv  = (const float4*)g_x2;
        float acc = 0.f;
        #pragma unroll 4
        for (int i = lane; i < N2 / 4; i += 32) acc += dot4(row[i], xv[i]);
        #pragma unroll
        for (int o = 16; o; o >>= 1) acc += __shfl_xor_sync(0xFFFFFFFFu, acc, o);
        if (lane == 0) {
            float e = g_x1[r] - tanhf(acc);
            local = e * e;
        }
    }

    if (lane == 0) s_part[warpInBlock] = local;
    __syncthreads();
    if (threadIdx.x == 0) {
        float s = 0.f;
        #pragma unroll
        for (int w = 0; w < 8; w++) s += s_part[w];
        atomicAdd(out, s);
    }
}

// ---------------------------------------------------------------------------
extern "C" void kernel_launch(void* const* d_in, const int* in_sizes, int n_in,
                              void* d_out, int out_size) {
    const float* x0 = (const float*)d_in[0];
    const float* W0 = (const float*)d_in[1];
    const float* W1 = (const float*)d_in[2];
    float* out = (float*)d_out;

    k_init<<<32, 256>>>(out);
    k_step1<<<256, 512>>>(x0, W0);                    // specialized step 1
    k_update<<<(N1 + N2) / 256, 256>>>();
    for (int s = 0; s < 8; s++) {
        k_step<<<256, 512>>>(x0, W0, W1);             // round-3 engine
        k_update<<<(N1 + N2) / 256, 256>>>();
    }
    k_final<<<(N0 + N1) / 8, 256>>>(x0, W0, W1, out); // final error
}